// round 7
// baseline (speedup 1.0000x reference)
#include <cuda_runtime.h>

#define IN_F   4096
#define OUT_F  11008
#define NC     16
#define TOPK   1024

#define MV_GRID   888                 // 148 SMs x 6 blocks
#define MV_WARPS  (MV_GRID * 8)       // 7104

__device__ float g_xmask[IN_F];
__device__ float g_d2[NC];
__device__ unsigned g_ctr;            // zero-initialized; reset by last block

// ---------------------------------------------------------------------------
// Kernel 1 (fused prep): 16 blocks x 1024 threads.
// Each block: bias->out slice, redundant softmax(|x|), d2 to its center.
// Last-finishing block: argmin + exact top-1024 radix select -> g_xmask.
// ---------------------------------------------------------------------------
__global__ void __launch_bounds__(1024)
prep_kernel(const float* __restrict__ x,
            const float* __restrict__ centers,
            const float* __restrict__ bias,
            float* __restrict__ out)
{
    __shared__ float    s_red[32];
    __shared__ float    s_b;
    __shared__ int      s_flag;
    __shared__ unsigned s_keys[IN_F];
    __shared__ unsigned s_hist[4][256];
    __shared__ unsigned s_wsum[8];
    __shared__ int      s_ints[3];    // [0]=ci [1]=remaining [2]=prefix
    __shared__ int      s_warp[32];

    const int tid  = threadIdx.x;
    const int lane = tid & 31;
    const int wid  = tid >> 5;
    const int c    = blockIdx.x;

    // ---- bias -> out init (covers 16*1024 >= 11008) ----
    const int gi = c * 1024 + tid;
    if (gi < OUT_F) out[gi] = bias[gi];

    // ---- softmax(|x|) (redundant per block, deterministic) ----
    const float4 xv = reinterpret_cast<const float4*>(x)[tid];
    const float4 cv = reinterpret_cast<const float4*>(centers)[c * (IN_F / 4) + tid];

    float a[4] = { fabsf(xv.x), fabsf(xv.y), fabsf(xv.z), fabsf(xv.w) };
    float m = fmaxf(fmaxf(a[0], a[1]), fmaxf(a[2], a[3]));
#pragma unroll
    for (int o = 16; o > 0; o >>= 1) m = fmaxf(m, __shfl_xor_sync(0xffffffffu, m, o));
    if (lane == 0) s_red[wid] = m;
    __syncthreads();
    if (wid == 0) {
        float r = s_red[lane];
#pragma unroll
        for (int o = 16; o > 0; o >>= 1) r = fmaxf(r, __shfl_xor_sync(0xffffffffu, r, o));
        if (lane == 0) s_b = r;
    }
    __syncthreads();
    m = s_b;
    __syncthreads();

    float e[4];
    float s = 0.f;
#pragma unroll
    for (int k = 0; k < 4; k++) { e[k] = expf(a[k] - m); s += e[k]; }
#pragma unroll
    for (int o = 16; o > 0; o >>= 1) s += __shfl_xor_sync(0xffffffffu, s, o);
    if (lane == 0) s_red[wid] = s;
    __syncthreads();
    if (wid == 0) {
        float r = s_red[lane];
#pragma unroll
        for (int o = 16; o > 0; o >>= 1) r += __shfl_xor_sync(0xffffffffu, r, o);
        if (lane == 0) s_b = r;
    }
    __syncthreads();
    const float inv_s = 1.f / s_b;

    // ---- d2 to center c ----
    float dx = cv.x - e[0] * inv_s;
    float dy = cv.y - e[1] * inv_s;
    float dz = cv.z - e[2] * inv_s;
    float dw = cv.w - e[3] * inv_s;
    float d2 = dx * dx + dy * dy + dz * dz + dw * dw;
#pragma unroll
    for (int o = 16; o > 0; o >>= 1) d2 += __shfl_xor_sync(0xffffffffu, d2, o);
    __syncthreads();
    if (lane == 0) s_red[wid] = d2;
    __syncthreads();
    if (tid == 0) {
        float r = 0.f;
#pragma unroll
        for (int w = 0; w < 32; w++) r += s_red[w];
        g_d2[c] = r;
        __threadfence();                       // publish g_d2 + bias writes
        unsigned old = atomicAdd(&g_ctr, 1u);
        s_flag = (old == NC - 1);
    }
    __syncthreads();
    if (!s_flag) return;

    // =============== last block: argmin + radix select ===============
    __threadfence();                           // acquire other blocks' g_d2
    ((unsigned*)s_hist)[tid] = 0u;             // clear 4 histograms
    if (tid == 0) {
        int best = 0;
        float bv = g_d2[0];
        for (int k = 1; k < NC; k++)
            if (g_d2[k] < bv) { bv = g_d2[k]; best = k; }   // first-min tie-break
        s_ints[0] = best;
        g_ctr = 0u;                            // reset for next replay
    }
    __syncthreads();

    const int base = tid * 4;
    {
        const int ci = s_ints[0];
        const float4 kv = reinterpret_cast<const float4*>(centers)[ci * (IN_F / 4) + tid];
        s_keys[base + 0] = __float_as_uint(kv.x);
        s_keys[base + 1] = __float_as_uint(kv.y);
        s_keys[base + 2] = __float_as_uint(kv.z);
        s_keys[base + 3] = __float_as_uint(kv.w);
    }
    __syncthreads();

    unsigned prefix    = 0;
    int      remaining = TOPK;
#pragma unroll
    for (int p = 0; p < 4; p++) {
        const int shift = 24 - 8 * p;
#pragma unroll
        for (int j = 0; j < 4; j++) {
            unsigned key = s_keys[base + j];
            bool match = (p == 0) ||
                         ((key >> (shift + 8)) == (prefix >> (shift + 8)));
            if (match) atomicAdd(&s_hist[p][(key >> shift) & 255u], 1u);
        }
        __syncthreads();
        unsigned v = 0, cnt = 0;
        if (tid < 256) {
            cnt = s_hist[p][tid];
            v = cnt;
#pragma unroll
            for (int off = 1; off < 32; off <<= 1) {
                unsigned n = __shfl_down_sync(0xffffffffu, v, off);
                if (lane + off < 32) v += n;
            }
            if (lane == 0) s_wsum[wid] = v;
        }
        __syncthreads();
        if (tid < 256) {
            unsigned off = 0;
            for (int w2 = wid + 1; w2 < 8; w2++) off += s_wsum[w2];
            unsigned ge = v + off;             // #keys byte >= tid (among matching)
            unsigned gt = ge - cnt;            // #keys byte >  tid
            if ((int)ge >= remaining && (int)gt < remaining) {   // unique crossing
                s_ints[1] = remaining - (int)gt;
                s_ints[2] = (int)(prefix | ((unsigned)tid << shift));
            }
        }
        __syncthreads();
        remaining = s_ints[1];
        prefix    = (unsigned)s_ints[2];
        __syncthreads();
    }
    const unsigned T = prefix;
    const int      R = remaining;              // R lowest-index ties (jax order)

    int cnt4[4];
    int tot = 0;
#pragma unroll
    for (int j = 0; j < 4; j++) {
        cnt4[j] = tot;
        tot += (s_keys[base + j] == T) ? 1 : 0;
    }
    int incl = tot;
#pragma unroll
    for (int off = 1; off < 32; off <<= 1) {
        int n = __shfl_up_sync(0xffffffffu, incl, off);
        if (lane >= off) incl += n;
    }
    if (lane == 31) s_warp[wid] = incl;
    __syncthreads();
    if (wid == 0) {
        int v = s_warp[lane];
#pragma unroll
        for (int off = 1; off < 32; off <<= 1) {
            int n = __shfl_up_sync(0xffffffffu, v, off);
            if (lane >= off) v += n;
        }
        s_warp[lane] = v;
    }
    __syncthreads();
    const int excl = incl - tot + (wid > 0 ? s_warp[wid - 1] : 0);
    const float xin[4] = { xv.x, xv.y, xv.z, xv.w };
    float o4[4];
#pragma unroll
    for (int j = 0; j < 4; j++) {
        unsigned key = s_keys[base + j];
        bool sel = (key > T) || (key == T && (excl + cnt4[j]) < R);
        o4[j] = sel ? xin[j] : 0.f;
    }
    reinterpret_cast<float4*>(g_xmask)[tid] = make_float4(o4[0], o4[1], o4[2], o4[3]);
}

// ---------------------------------------------------------------------------
// Kernel 2: out += W @ x_masked (out holds bias). Eighth-row work units:
// unit = (row, seg): 512 contiguous floats. 88064 units over 7104 warps ->
// 12-13 units/warp, ~95% load balance. Warp's seg fixed -> x loop-invariant.
// ---------------------------------------------------------------------------
__global__ void __launch_bounds__(256)
matvec_kernel(const float* __restrict__ W,
              float* __restrict__ out)
{
    __shared__ float4 sx[IN_F / 4];
    const int tid = threadIdx.x;
    for (int i = tid; i < IN_F / 4; i += 256)
        sx[i] = reinterpret_cast<const float4*>(g_xmask)[i];
    __syncthreads();

    const int warp = tid >> 5;
    const int lane = tid & 31;
    const int wg   = blockIdx.x * 8 + warp;    // 0 .. 7103
    const int seg  = wg & 7;                   // fixed 512-col segment
    const int row0 = wg >> 3;                  // 0 .. 887

    // loop-invariant x segment (4 float4 per lane)
    const float4* xr = sx + seg * 128;
    const float4 x0 = xr[lane];
    const float4 x1 = xr[lane + 32];
    const float4 x2 = xr[lane + 64];
    const float4 x3 = xr[lane + 96];

    const float4* W4 = reinterpret_cast<const float4*>(W);

#pragma unroll 2
    for (int row = row0; row < OUT_F; row += MV_GRID) {
        const float4* wr = W4 + (size_t)row * (IN_F / 4) + seg * 128;
        float4 w0 = wr[lane];
        float4 w1 = wr[lane + 32];
        float4 w2 = wr[lane + 64];
        float4 w3 = wr[lane + 96];
        float acc = w0.x * x0.x + w0.y * x0.y + w0.z * x0.z + w0.w * x0.w
                  + w1.x * x1.x + w1.y * x1.y + w1.z * x1.z + w1.w * x1.w
                  + w2.x * x2.x + w2.y * x2.y + w2.z * x2.z + w2.w * x2.w
                  + w3.x * x3.x + w3.y * x3.y + w3.z * x3.z + w3.w * x3.w;
#pragma unroll
        for (int o = 16; o > 0; o >>= 1)
            acc += __shfl_xor_sync(0xffffffffu, acc, o);
        if (lane == 0)
            atomicAdd(out + row, acc);
    }
}

// ---------------------------------------------------------------------------
extern "C" void kernel_launch(void* const* d_in, const int* in_sizes, int n_in,
                              void* d_out, int out_size)
{
    const float* x       = (const float*)d_in[0];  // [4096]
    const float* weight  = (const float*)d_in[1];  // [11008, 4096]
    const float* bias    = (const float*)d_in[2];  // [11008]
    const float* centers = (const float*)d_in[3];  // [16, 4096]
    float*       out     = (float*)d_out;          // [11008]

    prep_kernel<<<NC, 1024>>>(x, centers, bias, out);
    matvec_kernel<<<MV_GRID, 256>>>(weight, out);
}

// round 11
// speedup vs baseline: 1.0511x; 1.0511x over previous
#include <cuda_runtime.h>

#define IN_F   4096
#define OUT_F  11008
#define NC     16
#define TOPK   1024

__device__ float g_xmask[IN_F];
__device__ float g_d2[NC];
__device__ unsigned g_ctr;            // zero-init; reset by last prep block

// ---------------------------------------------------------------------------
// Kernel 1 (fused prep): 16 blocks x 1024 threads.
// Each block: redundant softmax(|x|), d2 to its center.
// Last-finishing block: argmin + exact top-1024 radix select -> g_xmask.
// (Structure identical to the R7 prep_kernel that passed; bias init removed.)
// ---------------------------------------------------------------------------
__global__ void __launch_bounds__(1024)
prep_kernel(const float* __restrict__ x,
            const float* __restrict__ centers)
{
    __shared__ float    s_red[32];
    __shared__ float    s_b;
    __shared__ int      s_flag;
    __shared__ unsigned s_keys[IN_F];
    __shared__ unsigned s_hist[4][256];
    __shared__ unsigned s_wsum[8];
    __shared__ int      s_ints[3];    // [0]=ci [1]=remaining [2]=prefix
    __shared__ int      s_warp[32];

    const int tid  = threadIdx.x;
    const int lane = tid & 31;
    const int wid  = tid >> 5;
    const int c    = blockIdx.x;

    // ---- softmax(|x|) (redundant per block, deterministic) ----
    const float4 xv = reinterpret_cast<const float4*>(x)[tid];
    const float4 cv = reinterpret_cast<const float4*>(centers)[c * (IN_F / 4) + tid];

    float a[4] = { fabsf(xv.x), fabsf(xv.y), fabsf(xv.z), fabsf(xv.w) };
    float m = fmaxf(fmaxf(a[0], a[1]), fmaxf(a[2], a[3]));
#pragma unroll
    for (int o = 16; o > 0; o >>= 1) m = fmaxf(m, __shfl_xor_sync(0xffffffffu, m, o));
    if (lane == 0) s_red[wid] = m;
    __syncthreads();
    if (wid == 0) {
        float r = s_red[lane];
#pragma unroll
        for (int o = 16; o > 0; o >>= 1) r = fmaxf(r, __shfl_xor_sync(0xffffffffu, r, o));
        if (lane == 0) s_b = r;
    }
    __syncthreads();
    m = s_b;
    __syncthreads();

    float e[4];
    float s = 0.f;
#pragma unroll
    for (int k = 0; k < 4; k++) { e[k] = expf(a[k] - m); s += e[k]; }
#pragma unroll
    for (int o = 16; o > 0; o >>= 1) s += __shfl_xor_sync(0xffffffffu, s, o);
    if (lane == 0) s_red[wid] = s;
    __syncthreads();
    if (wid == 0) {
        float r = s_red[lane];
#pragma unroll
        for (int o = 16; o > 0; o >>= 1) r += __shfl_xor_sync(0xffffffffu, r, o);
        if (lane == 0) s_b = r;
    }
    __syncthreads();
    const float inv_s = 1.f / s_b;

    // ---- d2 to center c ----
    float dx = cv.x - e[0] * inv_s;
    float dy = cv.y - e[1] * inv_s;
    float dz = cv.z - e[2] * inv_s;
    float dw = cv.w - e[3] * inv_s;
    float d2 = dx * dx + dy * dy + dz * dz + dw * dw;
#pragma unroll
    for (int o = 16; o > 0; o >>= 1) d2 += __shfl_xor_sync(0xffffffffu, d2, o);
    __syncthreads();
    if (lane == 0) s_red[wid] = d2;
    __syncthreads();
    if (tid == 0) {
        float r = 0.f;
#pragma unroll
        for (int w = 0; w < 32; w++) r += s_red[w];
        g_d2[c] = r;
        __threadfence();                       // publish g_d2
        unsigned old = atomicAdd(&g_ctr, 1u);
        s_flag = (old == NC - 1);
    }
    __syncthreads();
    if (!s_flag) return;

    // =============== last block: argmin + radix select ===============
    __threadfence();                           // acquire other blocks' g_d2
    ((unsigned*)s_hist)[tid] = 0u;             // clear 4 histograms
    if (tid == 0) {
        int best = 0;
        float bv = g_d2[0];
        for (int k = 1; k < NC; k++)
            if (g_d2[k] < bv) { bv = g_d2[k]; best = k; }   // first-min tie-break
        s_ints[0] = best;
        g_ctr = 0u;                            // reset for next replay
    }
    __syncthreads();

    const int base = tid * 4;
    {
        const int ci = s_ints[0];
        const float4 kv = reinterpret_cast<const float4*>(centers)[ci * (IN_F / 4) + tid];
        s_keys[base + 0] = __float_as_uint(kv.x);
        s_keys[base + 1] = __float_as_uint(kv.y);
        s_keys[base + 2] = __float_as_uint(kv.z);
        s_keys[base + 3] = __float_as_uint(kv.w);
    }
    __syncthreads();

    unsigned prefix    = 0;
    int      remaining = TOPK;
#pragma unroll
    for (int p = 0; p < 4; p++) {
        const int shift = 24 - 8 * p;
#pragma unroll
        for (int j = 0; j < 4; j++) {
            unsigned key = s_keys[base + j];
            bool match = (p == 0) ||
                         ((key >> (shift + 8)) == (prefix >> (shift + 8)));
            if (match) atomicAdd(&s_hist[p][(key >> shift) & 255u], 1u);
        }
        __syncthreads();
        unsigned v = 0, cnt = 0;
        if (tid < 256) {
            cnt = s_hist[p][tid];
            v = cnt;
#pragma unroll
            for (int off = 1; off < 32; off <<= 1) {
                unsigned n = __shfl_down_sync(0xffffffffu, v, off);
                if (lane + off < 32) v += n;
            }
            if (lane == 0) s_wsum[wid] = v;
        }
        __syncthreads();
        if (tid < 256) {
            unsigned off = 0;
            for (int w2 = wid + 1; w2 < 8; w2++) off += s_wsum[w2];
            unsigned ge = v + off;             // #keys byte >= tid (among matching)
            unsigned gt = ge - cnt;            // #keys byte >  tid
            if ((int)ge >= remaining && (int)gt < remaining) {   // unique crossing
                s_ints[1] = remaining - (int)gt;
                s_ints[2] = (int)(prefix | ((unsigned)tid << shift));
            }
        }
        __syncthreads();
        remaining = s_ints[1];
        prefix    = (unsigned)s_ints[2];
        __syncthreads();
    }
    const unsigned T = prefix;
    const int      R = remaining;              // R lowest-index ties (jax order)

    int cnt4[4];
    int tot = 0;
#pragma unroll
    for (int j = 0; j < 4; j++) {
        cnt4[j] = tot;
        tot += (s_keys[base + j] == T) ? 1 : 0;
    }
    int incl = tot;
#pragma unroll
    for (int off = 1; off < 32; off <<= 1) {
        int n = __shfl_up_sync(0xffffffffu, incl, off);
        if (lane >= off) incl += n;
    }
    if (lane == 31) s_warp[wid] = incl;
    __syncthreads();
    if (wid == 0) {
        int v = s_warp[lane];
#pragma unroll
        for (int off = 1; off < 32; off <<= 1) {
            int n = __shfl_up_sync(0xffffffffu, v, off);
            if (lane >= off) v += n;
        }
        s_warp[lane] = v;
    }
    __syncthreads();
    const int excl = incl - tot + (wid > 0 ? s_warp[wid - 1] : 0);
    const float xin[4] = { xv.x, xv.y, xv.z, xv.w };
    float o4[4];
#pragma unroll
    for (int j = 0; j < 4; j++) {
        unsigned key = s_keys[base + j];
        bool sel = (key > T) || (key == T && (excl + cnt4[j]) < R);
        o4[j] = sel ? xin[j] : 0.f;
    }
    reinterpret_cast<float4*>(g_xmask)[tid] = make_float4(o4[0], o4[1], o4[2], o4[3]);
}

// ---------------------------------------------------------------------------
// Kernel 2: out = W @ x_masked + bias.
// grid=688 x 256: 5504 warps, EXACTLY 2 rows per warp (zero imbalance),
// all blocks co-resident (4.65/SM; launch_bounds(256,5) caps regs at 51).
// 8 independent float4 loads per iteration (4 per row x 2 rows) for MLP.
// ---------------------------------------------------------------------------
__global__ void __launch_bounds__(256, 5)
matvec_kernel(const float* __restrict__ W,
              const float* __restrict__ bias,
              float* __restrict__ out)
{
    __shared__ float4 sx[IN_F / 4];
    const int tid = threadIdx.x;
    for (int i = tid; i < IN_F / 4; i += 256)
        sx[i] = reinterpret_cast<const float4*>(g_xmask)[i];
    __syncthreads();

    const int warp = tid >> 5;
    const int lane = tid & 31;
    const int row0 = (blockIdx.x * 8 + warp) * 2;   // 0..11006, always in range

    const float4* w0 = reinterpret_cast<const float4*>(W + (size_t)row0 * IN_F);
    const float4* w1 = w0 + (IN_F / 4);

    float acc0 = 0.f, acc1 = 0.f;
#pragma unroll 2
    for (int j0 = 0; j0 < IN_F / 4; j0 += 128) {
        const int j = j0 + lane;
        // 8 independent loads issued back-to-back
        float4 a0 = w0[j];      float4 a1 = w0[j + 32];
        float4 a2 = w0[j + 64]; float4 a3 = w0[j + 96];
        float4 b0 = w1[j];      float4 b1 = w1[j + 32];
        float4 b2 = w1[j + 64]; float4 b3 = w1[j + 96];
        float4 x0 = sx[j];      float4 x1 = sx[j + 32];
        float4 x2 = sx[j + 64]; float4 x3 = sx[j + 96];
        acc0 += a0.x * x0.x + a0.y * x0.y + a0.z * x0.z + a0.w * x0.w
              + a1.x * x1.x + a1.y * x1.y + a1.z * x1.z + a1.w * x1.w
              + a2.x * x2.x + a2.y * x2.y + a2.z * x2.z + a2.w * x2.w
              + a3.x * x3.x + a3.y * x3.y + a3.z * x3.z + a3.w * x3.w;
        acc1 += b0.x * x0.x + b0.y * x0.y + b0.z * x0.z + b0.w * x0.w
              + b1.x * x1.x + b1.y * x1.y + b1.z * x1.z + b1.w * x1.w
              + b2.x * x2.x + b2.y * x2.y + b2.z * x2.z + b2.w * x2.w
              + b3.x * x3.x + b3.y * x3.y + b3.z * x3.z + b3.w * x3.w;
    }
#pragma unroll
    for (int o = 16; o > 0; o >>= 1) {
        acc0 += __shfl_xor_sync(0xffffffffu, acc0, o);
        acc1 += __shfl_xor_sync(0xffffffffu, acc1, o);
    }
    if (lane == 0) {
        out[row0]     = acc0 + bias[row0];
        out[row0 + 1] = acc1 + bias[row0 + 1];
    }
}

// ---------------------------------------------------------------------------
extern "C" void kernel_launch(void* const* d_in, const int* in_sizes, int n_in,
                              void* d_out, int out_size)
{
    const float* x       = (const float*)d_in[0];  // [4096]
    const float* weight  = (const float*)d_in[1];  // [11008, 4096]
    const float* bias    = (const float*)d_in[2];  // [11008]
    const float* centers = (const float*)d_in[3];  // [16, 4096]
    float*       out     = (float*)d_out;          // [11008]

    prep_kernel<<<NC, 1024>>>(x, centers);
    matvec_kernel<<<OUT_F / 16, 256>>>(weight, bias, out);
}

// round 12
// speedup vs baseline: 1.1004x; 1.0468x over previous
#include <cuda_runtime.h>

#define IN_F   4096
#define OUT_F  11008
#define NC     16
#define TOPK   1024

__device__ float g_xmask[IN_F];
__device__ float g_d2[NC];
__device__ unsigned g_ctr;            // zero-init; reset by last prep block

// ---------------------------------------------------------------------------
// Kernel 1 (fused prep): 16 blocks x 1024 threads.
// Each block: redundant softmax(|x|), d2 to its center, then PDL-trigger.
// Last-finishing block: argmin + exact top-1024 radix select -> g_xmask.
// ---------------------------------------------------------------------------
__global__ void __launch_bounds__(1024)
prep_kernel(const float* __restrict__ x,
            const float* __restrict__ centers)
{
    __shared__ float    s_red[32];
    __shared__ float    s_b;
    __shared__ int      s_flag;
    __shared__ unsigned s_keys[IN_F];
    __shared__ unsigned s_hist[4][256];
    __shared__ unsigned s_wsum[8];
    __shared__ int      s_ints[3];    // [0]=ci [1]=remaining [2]=prefix
    __shared__ int      s_warp[32];

    const int tid  = threadIdx.x;
    const int lane = tid & 31;
    const int wid  = tid >> 5;
    const int c    = blockIdx.x;

    // ---- softmax(|x|) (redundant per block, deterministic) ----
    const float4 xv = reinterpret_cast<const float4*>(x)[tid];
    const float4 cv = reinterpret_cast<const float4*>(centers)[c * (IN_F / 4) + tid];

    float a[4] = { fabsf(xv.x), fabsf(xv.y), fabsf(xv.z), fabsf(xv.w) };
    float m = fmaxf(fmaxf(a[0], a[1]), fmaxf(a[2], a[3]));
#pragma unroll
    for (int o = 16; o > 0; o >>= 1) m = fmaxf(m, __shfl_xor_sync(0xffffffffu, m, o));
    if (lane == 0) s_red[wid] = m;
    __syncthreads();
    if (wid == 0) {
        float r = s_red[lane];
#pragma unroll
        for (int o = 16; o > 0; o >>= 1) r = fmaxf(r, __shfl_xor_sync(0xffffffffu, r, o));
        if (lane == 0) s_b = r;
    }
    __syncthreads();
    m = s_b;
    __syncthreads();

    float e[4];
    float s = 0.f;
#pragma unroll
    for (int k = 0; k < 4; k++) { e[k] = expf(a[k] - m); s += e[k]; }
#pragma unroll
    for (int o = 16; o > 0; o >>= 1) s += __shfl_xor_sync(0xffffffffu, s, o);
    if (lane == 0) s_red[wid] = s;
    __syncthreads();
    if (wid == 0) {
        float r = s_red[lane];
#pragma unroll
        for (int o = 16; o > 0; o >>= 1) r += __shfl_xor_sync(0xffffffffu, r, o);
        if (lane == 0) s_b = r;
    }
    __syncthreads();
    const float inv_s = 1.f / s_b;

    // ---- d2 to center c ----
    float dx = cv.x - e[0] * inv_s;
    float dy = cv.y - e[1] * inv_s;
    float dz = cv.z - e[2] * inv_s;
    float dw = cv.w - e[3] * inv_s;
    float d2 = dx * dx + dy * dy + dz * dz + dw * dw;
#pragma unroll
    for (int o = 16; o > 0; o >>= 1) d2 += __shfl_xor_sync(0xffffffffu, d2, o);
    __syncthreads();
    if (lane == 0) s_red[wid] = d2;
    __syncthreads();
    if (tid == 0) {
        float r = 0.f;
#pragma unroll
        for (int w = 0; w < 32; w++) r += s_red[w];
        g_d2[c] = r;
        __threadfence();                       // publish g_d2
        unsigned old = atomicAdd(&g_ctr, 1u);
        s_flag = (old == NC - 1);
        // PDL: this block's main work is done -> matvec grid may launch.
        // (Grid-dependency sync in matvec still waits for FULL completion,
        //  including the selector block's mask write below.)
        cudaTriggerProgrammaticLaunchCompletion();
    }
    __syncthreads();
    if (!s_flag) return;

    // =============== last block: argmin + radix select ===============
    __threadfence();                           // acquire other blocks' g_d2
    ((unsigned*)s_hist)[tid] = 0u;             // clear 4 histograms
    if (tid == 0) {
        int best = 0;
        float bv = g_d2[0];
        for (int k = 1; k < NC; k++)
            if (g_d2[k] < bv) { bv = g_d2[k]; best = k; }   // first-min tie-break
        s_ints[0] = best;
        g_ctr = 0u;                            // reset for next replay
    }
    __syncthreads();

    const int base = tid * 4;
    {
        const int ci = s_ints[0];
        const float4 kv = reinterpret_cast<const float4*>(centers)[ci * (IN_F / 4) + tid];
        s_keys[base + 0] = __float_as_uint(kv.x);
        s_keys[base + 1] = __float_as_uint(kv.y);
        s_keys[base + 2] = __float_as_uint(kv.z);
        s_keys[base + 3] = __float_as_uint(kv.w);
    }
    __syncthreads();

    unsigned prefix    = 0;
    int      remaining = TOPK;
#pragma unroll
    for (int p = 0; p < 4; p++) {
        const int shift = 24 - 8 * p;
#pragma unroll
        for (int j = 0; j < 4; j++) {
            unsigned key = s_keys[base + j];
            bool match = (p == 0) ||
                         ((key >> (shift + 8)) == (prefix >> (shift + 8)));
            if (match) atomicAdd(&s_hist[p][(key >> shift) & 255u], 1u);
        }
        __syncthreads();
        unsigned v = 0, cnt = 0;
        if (tid < 256) {
            cnt = s_hist[p][tid];
            v = cnt;
#pragma unroll
            for (int off = 1; off < 32; off <<= 1) {
                unsigned n = __shfl_down_sync(0xffffffffu, v, off);
                if (lane + off < 32) v += n;
            }
            if (lane == 0) s_wsum[wid] = v;
        }
        __syncthreads();
        if (tid < 256) {
            unsigned off = 0;
            for (int w2 = wid + 1; w2 < 8; w2++) off += s_wsum[w2];
            unsigned ge = v + off;             // #keys byte >= tid (among matching)
            unsigned gt = ge - cnt;            // #keys byte >  tid
            if ((int)ge >= remaining && (int)gt < remaining) {   // unique crossing
                s_ints[1] = remaining - (int)gt;
                s_ints[2] = (int)(prefix | ((unsigned)tid << shift));
            }
        }
        __syncthreads();
        remaining = s_ints[1];
        prefix    = (unsigned)s_ints[2];
        __syncthreads();
    }
    const unsigned T = prefix;
    const int      R = remaining;              // R lowest-index ties (jax order)

    int cnt4[4];
    int tot = 0;
#pragma unroll
    for (int j = 0; j < 4; j++) {
        cnt4[j] = tot;
        tot += (s_keys[base + j] == T) ? 1 : 0;
    }
    int incl = tot;
#pragma unroll
    for (int off = 1; off < 32; off <<= 1) {
        int n = __shfl_up_sync(0xffffffffu, incl, off);
        if (lane >= off) incl += n;
    }
    if (lane == 31) s_warp[wid] = incl;
    __syncthreads();
    if (wid == 0) {
        int v = s_warp[lane];
#pragma unroll
        for (int off = 1; off < 32; off <<= 1) {
            int n = __shfl_up_sync(0xffffffffu, v, off);
            if (lane >= off) v += n;
        }
        s_warp[lane] = v;
    }
    __syncthreads();
    const int excl = incl - tot + (wid > 0 ? s_warp[wid - 1] : 0);
    const float xin[4] = { xv.x, xv.y, xv.z, xv.w };
    float o4[4];
#pragma unroll
    for (int j = 0; j < 4; j++) {
        unsigned key = s_keys[base + j];
        bool sel = (key > T) || (key == T && (excl + cnt4[j]) < R);
        o4[j] = sel ? xin[j] : 0.f;
    }
    reinterpret_cast<float4*>(g_xmask)[tid] = make_float4(o4[0], o4[1], o4[2], o4[3]);
}

// ---------------------------------------------------------------------------
// Kernel 2: out = W @ x_masked + bias. R1's best-measured config verbatim
// (grid=1376, block=256, 1 row/warp, unroll 8), preceded by an L2 prefetch
// of the first 4KB of each warp's row + PDL grid-dependency sync.
// ---------------------------------------------------------------------------
__global__ void __launch_bounds__(256)
matvec_kernel(const float* __restrict__ W,
              const float* __restrict__ bias,
              float* __restrict__ out)
{
    __shared__ float4 sx[IN_F / 4];
    const int tid  = threadIdx.x;
    const int warp = tid >> 5;
    const int lane = tid & 31;
    const int row  = blockIdx.x * 8 + warp;   // 11008 = 1376 * 8, in range

    const float4* wr = reinterpret_cast<const float4*>(W + (size_t)row * IN_F);

    // ---- L2 prefetch of this warp's first 4 load groups (runs during prep) ----
    {
#pragma unroll
        for (int k = 0; k < 4; k++) {
            const float4* p = wr + lane + 32 * k;
            float pa, pb, pc, pd;
            asm volatile("ld.global.cg.v4.f32 {%0,%1,%2,%3}, [%4];"
                         : "=f"(pa), "=f"(pb), "=f"(pc), "=f"(pd)
                         : "l"(p));
        }
    }

    // ---- wait for prep grid completion (memory visible); no-op if serial ----
    cudaGridDependencySynchronize();

    for (int i = tid; i < IN_F / 4; i += 256)
        sx[i] = reinterpret_cast<const float4*>(g_xmask)[i];
    __syncthreads();

    float acc = 0.f;
#pragma unroll 8
    for (int j = lane; j < IN_F / 4; j += 32) {
        float4 w  = wr[j];
        float4 xv = sx[j];
        acc += w.x * xv.x + w.y * xv.y + w.z * xv.z + w.w * xv.w;
    }
#pragma unroll
    for (int o = 16; o > 0; o >>= 1)
        acc += __shfl_xor_sync(0xffffffffu, acc, o);
    if (lane == 0)
        out[row] = acc + bias[row];
}

// ---------------------------------------------------------------------------
extern "C" void kernel_launch(void* const* d_in, const int* in_sizes, int n_in,
                              void* d_out, int out_size)
{
    const float* x       = (const float*)d_in[0];  // [4096]
    const float* weight  = (const float*)d_in[1];  // [11008, 4096]
    const float* bias    = (const float*)d_in[2];  // [11008]
    const float* centers = (const float*)d_in[3];  // [16, 4096]
    float*       out     = (float*)d_out;          // [11008]

    prep_kernel<<<NC, 1024>>>(x, centers);

    // PDL launch: matvec may begin (prefetching) while prep's selector runs.
    cudaLaunchConfig_t cfg = {};
    cfg.gridDim  = dim3(OUT_F / 8);
    cfg.blockDim = dim3(256);
    cfg.stream   = 0;
    cudaLaunchAttribute attr[1];
    attr[0].id = cudaLaunchAttributeProgrammaticStreamSerialization;
    attr[0].val.programmaticStreamSerializationAllowed = 1;
    cfg.attrs    = attr;
    cfg.numAttrs = 1;
    cudaLaunchKernelEx(&cfg, matvec_kernel, weight, bias, out);
}

// round 13
// speedup vs baseline: 1.1563x; 1.0508x over previous
#include <cuda_runtime.h>

#define IN_F   4096
#define OUT_F  11008
#define NC     16
#define TOPK   1024

__device__ float g_masks[NC * IN_F];   // per-center masked-x candidates
__device__ float g_d2[NC];

// ---------------------------------------------------------------------------
// Kernel 1: 16 blocks x 1024 threads, fully independent (no inter-block sync).
// Block c: softmax(|x|) (redundant), d2 to center c -> g_d2[c] (+ PDL trigger),
// then exact top-1024 select of center c -> g_masks[c] (masked x).
// ---------------------------------------------------------------------------
__global__ void __launch_bounds__(1024)
prep_kernel(const float* __restrict__ x,
            const float* __restrict__ centers)
{
    __shared__ float    s_red[32];
    __shared__ float    s_b;
    __shared__ unsigned s_hist[4][256];
    __shared__ unsigned s_wsum[8];
    __shared__ int      s_ints[2];    // [0]=remaining [1]=prefix
    __shared__ int      s_warp[32];

    const int tid  = threadIdx.x;
    const int lane = tid & 31;
    const int wid  = tid >> 5;
    const int c    = blockIdx.x;

    ((unsigned*)s_hist)[tid] = 0u;    // clear all 4 histograms (1 entry/thread)

    // ---- loads (independent, issued together) ----
    const float4 xv = reinterpret_cast<const float4*>(x)[tid];
    const float4 cv = reinterpret_cast<const float4*>(centers)[c * (IN_F / 4) + tid];

    // ---- softmax(|x|), exact reference numerics ----
    float a[4] = { fabsf(xv.x), fabsf(xv.y), fabsf(xv.z), fabsf(xv.w) };
    float m = fmaxf(fmaxf(a[0], a[1]), fmaxf(a[2], a[3]));
#pragma unroll
    for (int o = 16; o > 0; o >>= 1) m = fmaxf(m, __shfl_xor_sync(0xffffffffu, m, o));
    if (lane == 0) s_red[wid] = m;
    __syncthreads();
    if (wid == 0) {
        float r = s_red[lane];
#pragma unroll
        for (int o = 16; o > 0; o >>= 1) r = fmaxf(r, __shfl_xor_sync(0xffffffffu, r, o));
        if (lane == 0) s_b = r;
    }
    __syncthreads();
    m = s_b;
    __syncthreads();

    float e[4];
    float s = 0.f;
#pragma unroll
    for (int k = 0; k < 4; k++) { e[k] = expf(a[k] - m); s += e[k]; }
#pragma unroll
    for (int o = 16; o > 0; o >>= 1) s += __shfl_xor_sync(0xffffffffu, s, o);
    if (lane == 0) s_red[wid] = s;
    __syncthreads();
    if (wid == 0) {
        float r = s_red[lane];
#pragma unroll
        for (int o = 16; o > 0; o >>= 1) r += __shfl_xor_sync(0xffffffffu, r, o);
        if (lane == 0) s_b = r;
    }
    __syncthreads();
    const float inv_s = 1.f / s_b;

    // ---- d2 to center c ----
    float dx = cv.x - e[0] * inv_s;
    float dy = cv.y - e[1] * inv_s;
    float dz = cv.z - e[2] * inv_s;
    float dw = cv.w - e[3] * inv_s;
    float d2 = dx * dx + dy * dy + dz * dz + dw * dw;
#pragma unroll
    for (int o = 16; o > 0; o >>= 1) d2 += __shfl_xor_sync(0xffffffffu, d2, o);
    __syncthreads();
    if (lane == 0) s_red[wid] = d2;
    __syncthreads();
    if (tid == 0) {
        float r = 0.f;
#pragma unroll
        for (int w = 0; w < 32; w++) r += s_red[w];
        g_d2[c] = r;
        // PDL: d2 published; matvec may launch & prefetch while we select.
        // (Its cudaGridDependencySynchronize still waits for FULL completion.)
        cudaTriggerProgrammaticLaunchCompletion();
    }

    // ---- local exact top-1024 select of center c (keys in registers) ----
    const unsigned key[4] = { __float_as_uint(cv.x), __float_as_uint(cv.y),
                              __float_as_uint(cv.z), __float_as_uint(cv.w) };

    unsigned prefix    = 0;
    int      remaining = TOPK;
#pragma unroll
    for (int p = 0; p < 4; p++) {
        const int shift = 24 - 8 * p;
#pragma unroll
        for (int j = 0; j < 4; j++) {
            bool match = (p == 0) ||
                         ((key[j] >> (shift + 8)) == (prefix >> (shift + 8)));
            if (match) atomicAdd(&s_hist[p][(key[j] >> shift) & 255u], 1u);
        }
        __syncthreads();
        unsigned v = 0, cnt = 0;
        if (tid < 256) {
            cnt = s_hist[p][tid];
            v = cnt;
#pragma unroll
            for (int off = 1; off < 32; off <<= 1) {
                unsigned n = __shfl_down_sync(0xffffffffu, v, off);
                if (lane + off < 32) v += n;
            }
            if (lane == 0) s_wsum[wid] = v;
        }
        __syncthreads();
        if (tid < 256) {
            unsigned off = 0;
            for (int w2 = wid + 1; w2 < 8; w2++) off += s_wsum[w2];
            unsigned ge = v + off;             // #keys byte >= tid (among matching)
            unsigned gt = ge - cnt;            // #keys byte >  tid
            if ((int)ge >= remaining && (int)gt < remaining) {   // unique crossing
                s_ints[0] = remaining - (int)gt;
                s_ints[1] = (int)(prefix | ((unsigned)tid << shift));
            }
        }
        __syncthreads();
        remaining = s_ints[0];
        prefix    = (unsigned)s_ints[1];
        __syncthreads();
    }
    const unsigned T = prefix;
    const int      R = remaining;              // R lowest-index ties (jax order)

    // tie-rank prefix scan (index order)
    int cnt4[4];
    int tot = 0;
#pragma unroll
    for (int j = 0; j < 4; j++) {
        cnt4[j] = tot;
        tot += (key[j] == T) ? 1 : 0;
    }
    int incl = tot;
#pragma unroll
    for (int off = 1; off < 32; off <<= 1) {
        int n = __shfl_up_sync(0xffffffffu, incl, off);
        if (lane >= off) incl += n;
    }
    if (lane == 31) s_warp[wid] = incl;
    __syncthreads();
    if (wid == 0) {
        int v = s_warp[lane];
#pragma unroll
        for (int off = 1; off < 32; off <<= 1) {
            int n = __shfl_up_sync(0xffffffffu, v, off);
            if (lane >= off) v += n;
        }
        s_warp[lane] = v;
    }
    __syncthreads();
    const int excl = incl - tot + (wid > 0 ? s_warp[wid - 1] : 0);
    const float xin[4] = { xv.x, xv.y, xv.z, xv.w };
    float o4[4];
#pragma unroll
    for (int j = 0; j < 4; j++) {
        bool sel = (key[j] > T) || (key[j] == T && (excl + cnt4[j]) < R);
        o4[j] = sel ? xin[j] : 0.f;
    }
    reinterpret_cast<float4*>(g_masks)[c * (IN_F / 4) + tid] =
        make_float4(o4[0], o4[1], o4[2], o4[3]);
}

// ---------------------------------------------------------------------------
// Kernel 2: out = W @ g_masks[argmin d2] + bias. R1's best-measured config
// (grid=1376, block=256, 1 row/warp, unroll 8). L2 prefetch + PDL sync, then
// per-block argmin (deterministic, identical in every block).
// ---------------------------------------------------------------------------
__global__ void __launch_bounds__(256)
matvec_kernel(const float* __restrict__ W,
              const float* __restrict__ bias,
              float* __restrict__ out)
{
    __shared__ float4 sx[IN_F / 4];
    __shared__ int    s_ci;
    const int tid  = threadIdx.x;
    const int warp = tid >> 5;
    const int lane = tid & 31;
    const int row  = blockIdx.x * 8 + warp;   // 11008 = 1376 * 8, in range

    const float4* wr = reinterpret_cast<const float4*>(W + (size_t)row * IN_F);

    // ---- L2 prefetch of this warp's first 2KB of W (runs during prep) ----
#pragma unroll
    for (int k = 0; k < 4; k++) {
        const float4* p = wr + lane + 32 * k;
        float pa, pb, pc, pd;
        asm volatile("ld.global.cg.v4.f32 {%0,%1,%2,%3}, [%4];"
                     : "=f"(pa), "=f"(pb), "=f"(pc), "=f"(pd)
                     : "l"(p));
    }

    // ---- wait for prep grid completion (memory visible); no-op if serial ----
    cudaGridDependencySynchronize();

    if (tid == 0) {
        int best = 0;
        float bv = g_d2[0];
#pragma unroll
        for (int k = 1; k < NC; k++)
            if (g_d2[k] < bv) { bv = g_d2[k]; best = k; }   // first-min tie-break
        s_ci = best;
    }
    __syncthreads();
    const float4* xm = reinterpret_cast<const float4*>(g_masks) + s_ci * (IN_F / 4);
    for (int i = tid; i < IN_F / 4; i += 256)
        sx[i] = xm[i];
    __syncthreads();

    float acc = 0.f;
#pragma unroll 8
    for (int j = lane; j < IN_F / 4; j += 32) {
        float4 w  = wr[j];
        float4 xv = sx[j];
        acc += w.x * xv.x + w.y * xv.y + w.z * xv.z + w.w * xv.w;
    }
#pragma unroll
    for (int o = 16; o > 0; o >>= 1)
        acc += __shfl_xor_sync(0xffffffffu, acc, o);
    if (lane == 0)
        out[row] = acc + bias[row];
}

// ---------------------------------------------------------------------------
extern "C" void kernel_launch(void* const* d_in, const int* in_sizes, int n_in,
                              void* d_out, int out_size)
{
    const float* x       = (const float*)d_in[0];  // [4096]
    const float* weight  = (const float*)d_in[1];  // [11008, 4096]
    const float* bias    = (const float*)d_in[2];  // [11008]
    const float* centers = (const float*)d_in[3];  // [16, 4096]
    float*       out     = (float*)d_out;          // [11008]

    prep_kernel<<<NC, 1024>>>(x, centers);

    // PDL launch: matvec begins (prefetching) while prep blocks run selects.
    cudaLaunchConfig_t cfg = {};
    cfg.gridDim  = dim3(OUT_F / 8);
    cfg.blockDim = dim3(256);
    cfg.stream   = 0;
    cudaLaunchAttribute attr[1];
    attr[0].id = cudaLaunchAttributeProgrammaticStreamSerialization;
    attr[0].val.programmaticStreamSerializationAllowed = 1;
    cfg.attrs    = attr;
    cfg.numAttrs = 1;
    cudaLaunchKernelEx(&cfg, matvec_kernel, weight, bias, out);
}